// round 6
// baseline (speedup 1.0000x reference)
#include <cuda_runtime.h>

// Problem shape (fixed by the dataset)
#define NB 64
#define NA 24564
#define NC 85                       // 4 loc + 81 conf
#define NROWS (NB * NA)             // 1,572,096
#define NCONF_PER_ROW 81u
#define NCONF ((unsigned)NROWS * NCONF_PER_ROW)   // 127,339,776 (divisible by 8)

#define CONF_THRESHOLD 0.01f
#define LOC_VAR 0.1f
#define SIZE_VAR 0.2f

// Fused kernel, 8 conf elements per thread:
//  - conf: thread t emits output floats [8t, 8t+8) as two aligned STG.128.
//    Row/col index computed once per thread (one div), then carry-incremented.
//    8 independent LDGs issued up front -> deep MLP.
//  - loc: block b's conf reads cover every sector of rows
//    [ceil(2048b/81), ceil(2048(b+1)/81)) (<=26 rows); threads 0..count-1
//    decode those boxes from L1/L2-resident data. No extra DRAM reads.
__global__ void __launch_bounds__(256) fused_kernel(
    const float* __restrict__ pred,
    const float4* __restrict__ dboxes,
    float4* __restrict__ out_loc,
    float4* __restrict__ out_conf)
{
    const unsigned tid = threadIdx.x;
    const unsigned b   = blockIdx.x;

    unsigned t  = b * 256u + tid;
    unsigned i0 = t * 8u;

    if (i0 < NCONF) {
        // Index of first element: one division, then increment with carry.
        unsigned row = i0 / NCONF_PER_ROW;       // mul-hi magic
        unsigned k   = i0 - row * NCONF_PER_ROW;

        // Front-batch 8 independent loads for MLP.
        float x[8];
        unsigned r_ = row, k_ = k;
#pragma unroll
        for (int j = 0; j < 8; j++) {
            x[j] = __ldcs(pred + (size_t)r_ * NC + 4 + k_);
            k_++;
            if (k_ == NCONF_PER_ROW) { k_ = 0; r_++; }
        }

        float v[8];
#pragma unroll
        for (int j = 0; j < 8; j++)
            v[j] = (x[j] > CONF_THRESHOLD) ? 1.0f : 0.0f;

        unsigned q = t * 2u;                     // float4 index
        __stcs(out_conf + q,     make_float4(v[0], v[1], v[2], v[3]));
        __stcs(out_conf + q + 1, make_float4(v[4], v[5], v[6], v[7]));
    }

    // ---- box decode for the rows this block's conf reads touched ----
    unsigned rs = (2048u * b + 80u) / 81u;           // ceil(2048b/81)
    unsigned re = (2048u * (b + 1u) + 80u) / 81u;    // ceil(2048(b+1)/81)
    if (re > (unsigned)NROWS) re = (unsigned)NROWS;
    unsigned count = re - rs;                        // <= 26

    if (tid < count) {
        unsigned r = rs + tid;
        unsigned anchor = r % (unsigned)NA;

        const float* p = pred + (size_t)r * NC;
        float l0 = __ldg(p + 0);
        float l1 = __ldg(p + 1);
        float l2 = __ldg(p + 2);
        float l3 = __ldg(p + 3);

        float4 db = __ldg(dboxes + anchor);          // (cx, cy, w, h) — L2-hot

        float cx = fmaf(l0 * LOC_VAR, db.z, db.x);
        float cy = fmaf(l1 * LOC_VAR, db.w, db.y);
        float w  = db.z * __expf(l2 * SIZE_VAR);
        float h  = db.w * __expf(l3 * SIZE_VAR);

        float4 box;
        box.x = cx - 0.5f * w;
        box.y = cy - 0.5f * h;
        box.z = cx + 0.5f * w;
        box.w = cy + 0.5f * h;
        out_loc[r] = box;
    }
}

extern "C" void kernel_launch(void* const* d_in, const int* in_sizes, int n_in,
                              void* d_out, int out_size)
{
    const float*  pred   = (const float*)d_in[0];
    const float4* dboxes = (const float4*)d_in[1];
    float* out = (float*)d_out;

    // Output layout: [loc (NROWS*4 floats) | conf (NROWS*81 floats)]
    float4* out_loc  = (float4*)out;
    float4* out_conf = (float4*)(out + (size_t)NROWS * 4);

    unsigned nthreads_total = NCONF / 8u;                  // 15,917,472
    unsigned blocks = (nthreads_total + 255u) / 256u;      // 62,178
    fused_kernel<<<blocks, 256>>>(pred, dboxes, out_loc, out_conf);
}

// round 12
// speedup vs baseline: 1.1404x; 1.1404x over previous
#include <cuda_runtime.h>

// Problem shape (fixed by the dataset)
#define NB 64
#define NA 24564
#define NC 85                       // 4 loc + 81 conf
#define NROWS (NB * NA)             // 1,572,096
#define NCONF_PER_ROW 81
#define NCONF ((unsigned)NROWS * NCONF_PER_ROW)   // 127,339,776 (divisible by 4)

#define CONF_THRESHOLD 0.01f
#define LOC_VAR 0.1f
#define SIZE_VAR 0.2f

// R3 structure (best known: 165.2us) + evict-first conf stores.
//  - conf: thread t emits output float4 [4t, 4t+4); 4 scalar L1-cached loads
//    (16B/lane span = sector-optimal, per R4 post-mortem), one STG.128 with
//    .cs hint (write-once stream, keep L2 for the read stream).
//  - loc: block b's conf reads already fetched every sector of rows
//    [ceil(1024b/81), ceil(1024(b+1)/81)); threads 0..count-1 decode those
//    boxes from L1/L2-resident data. No extra DRAM read traffic.
__global__ void __launch_bounds__(256) fused_kernel(
    const float* __restrict__ pred,
    const float4* __restrict__ dboxes,
    float4* __restrict__ out_loc,
    float4* __restrict__ out_conf)
{
    const unsigned tid = threadIdx.x;
    const unsigned b   = blockIdx.x;

    // ---- conf indicators (4 elems per thread, aligned float4 store) ----
    unsigned t  = b * 256u + tid;
    unsigned i0 = t * 4u;
    if (i0 < NCONF) {
        float v[4];
#pragma unroll
        for (int j = 0; j < 4; j++) {
            unsigned idx = i0 + (unsigned)j;
            unsigned row = idx / NCONF_PER_ROW;      // mul-hi magic
            unsigned k   = idx - row * NCONF_PER_ROW;
            float x = __ldg(pred + (size_t)row * NC + 4 + k);
            v[j] = (x > CONF_THRESHOLD) ? 1.0f : 0.0f;
        }
        __stcs(out_conf + t, make_float4(v[0], v[1], v[2], v[3]));
    }

    // ---- box decode for the rows this block's conf reads touched ----
    unsigned rs = (1024u * b + 80u) / 81u;           // ceil(1024b/81)
    unsigned re = (1024u * (b + 1u) + 80u) / 81u;    // ceil(1024(b+1)/81)
    if (re > (unsigned)NROWS) re = (unsigned)NROWS;
    unsigned count = re - rs;                        // <= 13

    if (tid < count) {
        unsigned r = rs + tid;
        unsigned anchor = r % (unsigned)NA;

        const float* p = pred + (size_t)r * NC;
        float l0 = __ldg(p + 0);
        float l1 = __ldg(p + 1);
        float l2 = __ldg(p + 2);
        float l3 = __ldg(p + 3);

        float4 db = __ldg(dboxes + anchor);          // (cx, cy, w, h) — L2-hot

        float cx = fmaf(l0 * LOC_VAR, db.z, db.x);
        float cy = fmaf(l1 * LOC_VAR, db.w, db.y);
        float w  = db.z * __expf(l2 * SIZE_VAR);
        float h  = db.w * __expf(l3 * SIZE_VAR);

        float4 box;
        box.x = cx - 0.5f * w;
        box.y = cy - 0.5f * h;
        box.z = cx + 0.5f * w;
        box.w = cy + 0.5f * h;
        out_loc[r] = box;
    }
}

extern "C" void kernel_launch(void* const* d_in, const int* in_sizes, int n_in,
                              void* d_out, int out_size)
{
    const float*  pred   = (const float*)d_in[0];
    const float4* dboxes = (const float4*)d_in[1];
    float* out = (float*)d_out;

    // Output layout: [loc (NROWS*4 floats) | conf (NROWS*81 floats)]
    float4* out_loc  = (float4*)out;
    float4* out_conf = (float4*)(out + (size_t)NROWS * 4);

    unsigned nthreads_total = NCONF / 4u;                  // 31,834,944
    unsigned blocks = (nthreads_total + 255u) / 256u;      // 124,356
    fused_kernel<<<blocks, 256>>>(pred, dboxes, out_loc, out_conf);
}

// round 17
// speedup vs baseline: 1.1564x; 1.0140x over previous
#include <cuda_runtime.h>

// Problem shape (fixed by the dataset)
#define NB 64
#define NA 24564
#define NC 85                       // 4 loc + 81 conf
#define NROWS (NB * NA)             // 1,572,096
#define NCONF_PER_ROW 81u
#define NCONF ((unsigned)NROWS * NCONF_PER_ROW)   // 127,339,776 (divisible by 4)

#define CONF_THRESHOLD 0.01f
#define LOC_VAR 0.1f
#define SIZE_VAR 0.2f

// R3 structure (best measured: 165.2us), plain stores (R6 showed .cs hint is
// neutral/negative), with ONE division per thread + carry-increment indexing
// (R4 post-mortem: 4 elems/thread = sector-optimal; the regression there came
// from 8-wide loads + L1 bypass, not from carry-increment indexing).
//  - conf: thread t emits output float4 [4t, 4t+4); 4 scalar L1-cached loads
//    (16B/lane warp span = 4 sectors/LDG), one aligned STG.128.
//  - loc: block b's conf reads already fetched every sector of rows
//    [ceil(1024b/81), ceil(1024(b+1)/81)); threads 0..count-1 decode those
//    boxes from L1/L2-resident data. No extra DRAM read traffic.
__global__ void __launch_bounds__(256) fused_kernel(
    const float* __restrict__ pred,
    const float4* __restrict__ dboxes,
    float4* __restrict__ out_loc,
    float4* __restrict__ out_conf)
{
    const unsigned tid = threadIdx.x;
    const unsigned b   = blockIdx.x;

    // ---- conf indicators (4 elems per thread, aligned float4 store) ----
    unsigned t  = b * 256u + tid;
    unsigned i0 = t * 4u;
    if (i0 < NCONF) {
        // One division; remaining three indices by carry-increment.
        unsigned row = i0 / NCONF_PER_ROW;           // mul-hi magic, once
        unsigned k   = i0 - row * NCONF_PER_ROW;

        float x[4];
        {
            unsigned r_ = row, k_ = k;
#pragma unroll
            for (int j = 0; j < 4; j++) {
                x[j] = __ldg(pred + (size_t)r_ * NC + 4u + k_);
                k_++;
                if (k_ == NCONF_PER_ROW) { k_ = 0u; r_++; }
            }
        }

        float4 v;
        v.x = (x[0] > CONF_THRESHOLD) ? 1.0f : 0.0f;
        v.y = (x[1] > CONF_THRESHOLD) ? 1.0f : 0.0f;
        v.z = (x[2] > CONF_THRESHOLD) ? 1.0f : 0.0f;
        v.w = (x[3] > CONF_THRESHOLD) ? 1.0f : 0.0f;
        out_conf[t] = v;
    }

    // ---- box decode for the rows this block's conf reads touched ----
    unsigned rs = (1024u * b + 80u) / 81u;           // ceil(1024b/81)
    unsigned re = (1024u * (b + 1u) + 80u) / 81u;    // ceil(1024(b+1)/81)
    if (re > (unsigned)NROWS) re = (unsigned)NROWS;
    unsigned count = re - rs;                        // <= 13

    if (tid < count) {
        unsigned r = rs + tid;
        unsigned anchor = r % (unsigned)NA;

        const float* p = pred + (size_t)r * NC;
        float l0 = __ldg(p + 0);
        float l1 = __ldg(p + 1);
        float l2 = __ldg(p + 2);
        float l3 = __ldg(p + 3);

        float4 db = __ldg(dboxes + anchor);          // (cx, cy, w, h) — L2-hot

        float cx = fmaf(l0 * LOC_VAR, db.z, db.x);
        float cy = fmaf(l1 * LOC_VAR, db.w, db.y);
        float w  = db.z * __expf(l2 * SIZE_VAR);
        float h  = db.w * __expf(l3 * SIZE_VAR);

        float4 box;
        box.x = cx - 0.5f * w;
        box.y = cy - 0.5f * h;
        box.z = cx + 0.5f * w;
        box.w = cy + 0.5f * h;
        out_loc[r] = box;
    }
}

extern "C" void kernel_launch(void* const* d_in, const int* in_sizes, int n_in,
                              void* d_out, int out_size)
{
    const float*  pred   = (const float*)d_in[0];
    const float4* dboxes = (const float4*)d_in[1];
    float* out = (float*)d_out;

    // Output layout: [loc (NROWS*4 floats) | conf (NROWS*81 floats)]
    float4* out_loc  = (float4*)out;
    float4* out_conf = (float4*)(out + (size_t)NROWS * 4);

    unsigned nthreads_total = NCONF / 4u;                  // 31,834,944
    unsigned blocks = (nthreads_total + 255u) / 256u;      // 124,356
    fused_kernel<<<blocks, 256>>>(pred, dboxes, out_loc, out_conf);
}